// round 8
// baseline (speedup 1.0000x reference)
#include <cuda_runtime.h>
#include <math.h>

// Problem constants (fixed by the reference)
#define S_SZ  4096
#define D_SZ  300
#define C_SZ  4
#define D4    75            // float4 per embedding row
#define NB    128           // blocks (fully resident, 1/SM)
#define RPB   32            // sequence rows per block
#define NT    512           // threads per block (16 warps)
#define MBLK  30            // blocks computing mid (10 rows each); t on 30..59

// Scratch (device globals; no allocation allowed)
__device__ float    g_part1[D_SZ * NB];   // transposed [d][b]
__device__ float    g_mid[D_SZ];
__device__ float    g_t[D_SZ];
__device__ float    g_w2mid[C_SZ];
__device__ float    g_psum[NB];           // per-block unnormalized exp sums
__device__ float    g_y[C_SZ * NB];       // per-block W2 . (unnorm weighted sum)
__device__ unsigned g_cnt[4];             // zero-init; self-resetting
__device__ unsigned g_gen[4];             // monotonic (graph-replay safe)

__device__ __forceinline__ float warp_sum(float p) {
    #pragma unroll
    for (int o = 16; o > 0; o >>= 1) p += __shfl_xor_sync(0xFFFFFFFFu, p, o);
    return p;
}

// Grid barrier #i. acq_rel arrival; waiters spin on ld.acquire of gen word.
// Each block arrives exactly once per launch; count self-resets pre-bump.
__device__ __forceinline__ void gbar(int i) {
    __syncthreads();
    if (threadIdx.x == 0) {
        unsigned g;
        asm volatile("ld.relaxed.gpu.u32 %0,[%1];"
                     : "=r"(g) : "l"(&g_gen[i]) : "memory");
        unsigned old;
        asm volatile("atom.acq_rel.gpu.add.u32 %0,[%1],%2;"
                     : "=r"(old) : "l"(&g_cnt[i]), "r"(1u) : "memory");
        if (old == NB - 1) {
            asm volatile("st.relaxed.gpu.u32 [%0],%1;"
                         :: "l"(&g_cnt[i]), "r"(0u) : "memory");
            unsigned d;
            asm volatile("atom.acq_rel.gpu.add.u32 %0,[%1],%2;"
                         : "=r"(d) : "l"(&g_gen[i]), "r"(1u) : "memory");
        } else {
            unsigned cur;
            do {
                asm volatile("ld.acquire.gpu.u32 %0,[%1];"
                             : "=r"(cur) : "l"(&g_gen[i]) : "memory");
            } while (cur == g);
        }
    }
    __syncthreads();
}

__device__ __forceinline__ float dot4(float4 a, float4 b) {
    return fmaf(a.x, b.x, fmaf(a.y, b.y, fmaf(a.z, b.z, a.w * b.w)));
}

// Warp dot of a preloaded 300-float row (3 float4/lane) with an smem vector.
__device__ __forceinline__ float warp_dot_pre(float4 a0, float4 a1, float4 a2,
                                              const float4* __restrict__ v4,
                                              int lane) {
    float p = dot4(a0, v4[lane]) + dot4(a1, v4[lane + 32]);
    if (lane < D4 - 64) p += dot4(a2, v4[lane + 64]);
    return warp_sum(p);
}

// ---------------------------------------------------------------------------
__global__ __launch_bounds__(NT)
void fused(const int* __restrict__ x, const float* __restrict__ emb,
           const float* __restrict__ W1, const float* __restrict__ b1,
           const float* __restrict__ Wb, const float* __restrict__ bb,
           const float* __restrict__ W2, const float* __restrict__ b2,
           float* __restrict__ out)
{
    const int b = blockIdx.x, tid = threadIdx.x;
    const int lane = tid & 31, w = tid >> 5;

    __shared__ float4 s_emb[RPB][D4];   // staged embedding rows (38.4 KB)
    __shared__ float4 s_acc[4][D4];
    __shared__ float4 s_v4[D4 + 1];
    __shared__ float  s_sc[RPB];
    __shared__ float  s_e[RPB];
    __shared__ float  s_bc;
    __shared__ int    s_idx[RPB];
    float* s_v = (float*)s_v4;

    if (tid < RPB) s_idx[tid] = __ldg(&x[b * RPB + tid]);
    __syncthreads();

    // ---- Register preloads (issued during the DRAM gather; no barrier dep)
    float4 z = make_float4(0.f, 0.f, 0.f, 0.f);
    float4 wa0 = z, wa1 = z, wa2 = z;   // this block's W1 or Wb row (w<10)
    float4 wc0 = z, wc1 = z, wc2 = z;   // W2 row w (w<4), all blocks
    if (w < 10) {
        const float4* wr = 0;
        if (b < MBLK)               wr = (const float4*)(W1 + (long)(b * 10 + w) * D_SZ);
        else if (b < 2 * MBLK)      wr = (const float4*)(Wb + (long)((b - MBLK) * 10 + w) * D_SZ);
        if (wr) {
            wa0 = __ldg(&wr[lane]);
            wa1 = __ldg(&wr[lane + 32]);
            if (lane < D4 - 64) wa2 = __ldg(&wr[lane + 64]);
        }
    }
    if (w < C_SZ) {
        const float4* wr = (const float4*)(W2 + (long)w * D_SZ);
        wc0 = __ldg(&wr[lane]);
        wc1 = __ldg(&wr[lane + 32]);
        if (lane < D4 - 64) wc2 = __ldg(&wr[lane + 64]);
    }

    const float4* emb4 = (const float4*)emb;

    // ---- Phase A: gather 32 rows (DRAM) into smem + per-block partial sums
    if (tid < D_SZ) {
        const int c = tid % D4, g = tid / D4;
        float4 acc = z;
        #pragma unroll
        for (int k = 0; k < 8; k++) {
            const int r = g * 8 + k;
            float4 v = __ldg(&emb4[(long)s_idx[r] * D4 + c]);
            s_emb[r][c] = v;
            acc.x += v.x; acc.y += v.y; acc.z += v.z; acc.w += v.w;
        }
        s_acc[g][c] = acc;
    }
    __syncthreads();
    if (tid < D4) {
        float4 t0 = s_acc[0][tid], t1 = s_acc[1][tid];
        float4 t2 = s_acc[2][tid], t3 = s_acc[3][tid];
        g_part1[(4 * tid + 0) * NB + b] = (t0.x + t1.x) + (t2.x + t3.x);
        g_part1[(4 * tid + 1) * NB + b] = (t0.y + t1.y) + (t2.y + t3.y);
        g_part1[(4 * tid + 2) * NB + b] = (t0.z + t1.z) + (t2.z + t3.z);
        g_part1[(4 * tid + 3) * NB + b] = (t0.w + t1.w) + (t2.w + t3.w);
    }
    gbar(0);

    // ---- Phase B (blocks 0..29): redundant dense reduce + 10 mid rows each
    if (b < MBLK) {
        if (tid < D_SZ) {
            const float4* pr = (const float4*)(g_part1 + (long)tid * NB);
            float a0 = 0, a1 = 0, a2 = 0, a3 = 0;
            #pragma unroll 8
            for (int j = 0; j < NB / 4; j++) {
                float4 v = __ldg(&pr[j]);
                a0 += v.x; a1 += v.y; a2 += v.z; a3 += v.w;
            }
            s_v[tid] = ((a0 + a1) + (a2 + a3)) * (1.0f / S_SZ);
        }
        __syncthreads();
        if (w < 10) {
            float p = warp_dot_pre(wa0, wa1, wa2, s_v4, lane);
            if (lane == 0) g_mid[b * 10 + w] = p + __ldg(&b1[b * 10 + w]);
        }
    }
    gbar(1);

    // ---- Phase C (blocks 30..59): 10 t rows each; block 60: W2*mid
    if (b >= MBLK && b < 2 * MBLK) {
        for (int d = tid; d < D_SZ; d += NT) s_v[d] = g_mid[d];
        __syncthreads();
        if (w < 10) {
            float p = warp_dot_pre(wa0, wa1, wa2, s_v4, lane);
            if (lane == 0) g_t[(b - MBLK) * 10 + w] = p;
        }
    } else if (b == 2 * MBLK) {
        for (int d = tid; d < D_SZ; d += NT) s_v[d] = g_mid[d];
        __syncthreads();
        if (w < C_SZ) {
            float p = warp_dot_pre(wc0, wc1, wc2, s_v4, lane);
            if (lane == 0) g_w2mid[w] = p;
        }
    }
    gbar(2);

    // ---- Phase D (all blocks): scores, exp, psum, weighted sum, y — all smem
    for (int d = tid; d < D_SZ; d += NT) s_v[d] = g_t[d];
    __syncthreads();
    {
        const float bias = __ldg(bb);
        #pragma unroll
        for (int j = 0; j < 2; j++) {
            const int r = w * 2 + j;
            float p = dot4(s_emb[r][lane], s_v4[lane])
                    + dot4(s_emb[r][lane + 32], s_v4[lane + 32]);
            if (lane < D4 - 64) p += dot4(s_emb[r][lane + 64], s_v4[lane + 64]);
            p = warp_sum(p);
            if (lane == 0) s_sc[r] = p + bias;
        }
    }
    __syncthreads();
    if (w == 0) {                   // scores tiny -> unshifted exp exact-safe
        float e = expf(s_sc[lane]);
        s_e[lane] = e;
        float ps = warp_sum(e);
        if (lane == 0) g_psum[b] = ps;
    }
    __syncthreads();
    if (tid < D_SZ) {               // weighted sum with raw e, from smem
        const int c = tid % D4, g = tid / D4;
        float4 acc = z;
        #pragma unroll
        for (int k = 0; k < 8; k++) {
            const int r = g * 8 + k;
            const float wt = s_e[r];
            float4 v = s_emb[r][c];
            acc.x = fmaf(wt, v.x, acc.x); acc.y = fmaf(wt, v.y, acc.y);
            acc.z = fmaf(wt, v.z, acc.z); acc.w = fmaf(wt, v.w, acc.w);
        }
        s_acc[g][c] = acc;
    }
    __syncthreads();
    if (tid < D4) {                 // t no longer needed: reuse s_v4
        float4 t0 = s_acc[0][tid], t1 = s_acc[1][tid];
        float4 t2 = s_acc[2][tid], t3 = s_acc[3][tid];
        s_v4[tid] = make_float4((t0.x + t1.x) + (t2.x + t3.x),
                                (t0.y + t1.y) + (t2.y + t3.y),
                                (t0.z + t1.z) + (t2.z + t3.z),
                                (t0.w + t1.w) + (t2.w + t3.w));
    }
    __syncthreads();
    if (w < C_SZ) {
        float p = warp_dot_pre(wc0, wc1, wc2, s_v4, lane);
        if (lane == 0) g_y[w * NB + b] = p;
    }
    gbar(3);

    // ---- Phase E: redundant total (identical order), rewards, logits
    if (w == 0) {
        float v = (g_psum[lane] + g_psum[lane + 32])
                + (g_psum[lane + 64] + g_psum[lane + 96]);
        v = warp_sum(v);
        if (lane == 0) s_bc = 1.0f / v;
    }
    __syncthreads();
    const float inv = s_bc;
    if (tid < RPB)
        out[C_SZ + b * RPB + tid] = s_e[tid] * inv;

    if (b == 0 && w < C_SZ) {
        const float* yy = g_y + (long)w * NB;
        float v = (yy[lane] + yy[lane + 32]) + (yy[lane + 64] + yy[lane + 96]);
        v = warp_sum(v);
        if (lane == 0)
            out[w] = g_w2mid[w] + v * inv * (1.0f / S_SZ) + __ldg(&b2[w]);
    }
}

// ---------------------------------------------------------------------------
extern "C" void kernel_launch(void* const* d_in, const int* in_sizes, int n_in,
                              void* d_out, int out_size)
{
    const int*   x   = (const int*)  d_in[0];
    const float* emb = (const float*)d_in[1];
    const float* W1  = (const float*)d_in[2];
    const float* b1  = (const float*)d_in[3];
    const float* Wb  = (const float*)d_in[4];
    const float* bb  = (const float*)d_in[5];
    const float* W2  = (const float*)d_in[6];
    const float* b2  = (const float*)d_in[7];
    float* out = (float*)d_out;   // out[0:4] = output, out[4:4100] = reward

    fused<<<NB, NT>>>(x, emb, W1, b1, Wb, bb, W2, b2, out);
}

// round 9
// speedup vs baseline: 1.2183x; 1.2183x over previous
#include <cuda_runtime.h>
#include <math.h>

// Problem constants (fixed by the reference)
#define S_SZ  4096
#define D_SZ  300
#define C_SZ  4
#define D4    75            // float4 per embedding row
#define NB    128           // blocks (fully resident)
#define RPB   32            // sequence rows per block
#define NT    512           // threads per block (16 warps)

// Scratch (device globals; no allocation allowed)
__device__ float    g_part1[D_SZ * NB];   // transposed [d][b]
__device__ float    g_dense[D_SZ];
__device__ float    g_mid[D_SZ];
__device__ float    g_t[D_SZ];
__device__ float    g_w2mid[C_SZ];
__device__ float    g_psum[NB];           // per-block unnormalized exp sums
__device__ float    g_y[C_SZ * NB];       // per-block W2 . (unnorm weighted sum)
__device__ unsigned g_cnt[5];             // zero-init; self-resetting
__device__ unsigned g_gen[5];             // monotonic (graph-replay safe)

__device__ __forceinline__ float warp_sum(float p) {
    #pragma unroll
    for (int o = 16; o > 0; o >>= 1) p += __shfl_xor_sync(0xFFFFFFFFu, p, o);
    return p;
}

// Grid barrier #i. acq_rel arrival; waiters spin (with nanosleep backoff) on
// ld.acquire of the generation word. Each block arrives exactly once per
// launch; count self-resets before the gen bump -> graph-replay safe.
__device__ __forceinline__ void gbar(int i) {
    __syncthreads();
    if (threadIdx.x == 0) {
        unsigned g;
        asm volatile("ld.relaxed.gpu.u32 %0,[%1];"
                     : "=r"(g) : "l"(&g_gen[i]) : "memory");
        unsigned old;
        asm volatile("atom.acq_rel.gpu.add.u32 %0,[%1],%2;"
                     : "=r"(old) : "l"(&g_cnt[i]), "r"(1u) : "memory");
        if (old == NB - 1) {
            asm volatile("st.relaxed.gpu.u32 [%0],%1;"
                         :: "l"(&g_cnt[i]), "r"(0u) : "memory");
            unsigned d;
            asm volatile("atom.acq_rel.gpu.add.u32 %0,[%1],%2;"
                         : "=r"(d) : "l"(&g_gen[i]), "r"(1u) : "memory");
        } else {
            unsigned cur;
            do {
                __nanosleep(32);
                asm volatile("ld.acquire.gpu.u32 %0,[%1];"
                             : "=r"(cur) : "l"(&g_gen[i]) : "memory");
            } while (cur == g);
        }
    }
    __syncthreads();
}

__device__ __forceinline__ float dot4(float4 a, float4 b) {
    return fmaf(a.x, b.x, fmaf(a.y, b.y, fmaf(a.z, b.z, a.w * b.w)));
}

// Warp dot of a preloaded 300-float row (3 float4/lane) with an smem vector.
__device__ __forceinline__ float warp_dot_pre(float4 a0, float4 a1, float4 a2,
                                              const float4* __restrict__ v4,
                                              int lane) {
    float p = dot4(a0, v4[lane]) + dot4(a1, v4[lane + 32]);
    if (lane < D4 - 64) p += dot4(a2, v4[lane + 64]);
    return warp_sum(p);
}

// ---------------------------------------------------------------------------
__global__ __launch_bounds__(NT)
void fused(const int* __restrict__ x, const float* __restrict__ emb,
           const float* __restrict__ W1, const float* __restrict__ b1,
           const float* __restrict__ Wb, const float* __restrict__ bb,
           const float* __restrict__ W2, const float* __restrict__ b2,
           float* __restrict__ out)
{
    const int b = blockIdx.x, tid = threadIdx.x;
    const int lane = tid & 31, w = tid >> 5;

    __shared__ float4 s_emb[RPB][D4];   // staged embedding rows (38.4 KB)
    __shared__ float4 s_acc[4][D4];
    __shared__ float4 s_v4[D4 + 1];
    __shared__ float  s_sc[RPB];
    __shared__ float  s_e[RPB];
    __shared__ float  s_bc;
    __shared__ int    s_idx[RPB];
    float* s_v = (float*)s_v4;

    if (tid < RPB) s_idx[tid] = __ldg(&x[b * RPB + tid]);
    __syncthreads();

    // ---- Register preloads (concurrent with the DRAM gather, no barrier dep)
    const float4 z = make_float4(0.f, 0.f, 0.f, 0.f);
    float4 wA0 = z, wA1 = z, wA2 = z;       // W1 row d (warps 0-2)
    float4 wB0 = z, wB1 = z, wB2 = z;       // Wb row d (warps 0-2)
    float4 wC0 = z, wC1 = z, wC2 = z;       // W2 row (warps 4-7)
    float  b1v = 0.f;
    const int drow = w * NB + b;            // matvec row owned by warps 0-2
    if (w < 3 && drow < D_SZ) {
        const float4* wr1 = (const float4*)(W1 + (long)drow * D_SZ);
        const float4* wrb = (const float4*)(Wb + (long)drow * D_SZ);
        wA0 = __ldg(&wr1[lane]);  wA1 = __ldg(&wr1[lane + 32]);
        wB0 = __ldg(&wrb[lane]);  wB1 = __ldg(&wrb[lane + 32]);
        if (lane < D4 - 64) { wA2 = __ldg(&wr1[lane + 64]); wB2 = __ldg(&wrb[lane + 64]); }
        b1v = __ldg(&b1[drow]);
    }
    if (w >= 4 && w < 4 + C_SZ) {
        const float4* wr2 = (const float4*)(W2 + (long)(w - 4) * D_SZ);
        wC0 = __ldg(&wr2[lane]);  wC1 = __ldg(&wr2[lane + 32]);
        if (lane < D4 - 64) wC2 = __ldg(&wr2[lane + 64]);
    }

    const float4* emb4 = (const float4*)emb;

    // ---- Phase A: gather 32 rows (DRAM) -> smem stage + per-block partials
    if (tid < D_SZ) {
        const int c = tid % D4, g = tid / D4;
        float4 acc = z;
        #pragma unroll
        for (int k = 0; k < 8; k++) {
            const int r = g * 8 + k;
            float4 v = __ldg(&emb4[(long)s_idx[r] * D4 + c]);
            s_emb[r][c] = v;
            acc.x += v.x; acc.y += v.y; acc.z += v.z; acc.w += v.w;
        }
        s_acc[g][c] = acc;
    }
    __syncthreads();
    if (tid < D4) {
        float4 t0 = s_acc[0][tid], t1 = s_acc[1][tid];
        float4 t2 = s_acc[2][tid], t3 = s_acc[3][tid];
        g_part1[(4 * tid + 0) * NB + b] = (t0.x + t1.x) + (t2.x + t3.x);
        g_part1[(4 * tid + 1) * NB + b] = (t0.y + t1.y) + (t2.y + t3.y);
        g_part1[(4 * tid + 2) * NB + b] = (t0.z + t1.z) + (t2.z + t3.z);
        g_part1[(4 * tid + 3) * NB + b] = (t0.w + t1.w) + (t2.w + t3.w);
    }
    gbar(0);

    // ---- Phase B: dense[d] (warp-per-d, spread: block b owns d = w*128+b)
    if (w < 3 && drow < D_SZ) {
        const float* pp = g_part1 + (long)drow * NB;
        float v = (pp[lane] + pp[lane + 32]) + (pp[lane + 64] + pp[lane + 96]);
        v = warp_sum(v);
        if (lane == 0) g_dense[drow] = v * (1.0f / S_SZ);
    }
    gbar(1);

    // ---- Phase C: mid = W1*dense + b1 (preloaded rows, smem vector)
    for (int d = tid; d < D_SZ; d += NT) s_v[d] = g_dense[d];
    __syncthreads();
    if (w < 3 && drow < D_SZ) {
        float p = warp_dot_pre(wA0, wA1, wA2, s_v4, lane);
        if (lane == 0) g_mid[drow] = p + b1v;
    }
    gbar(2);

    // ---- Phase D: t = Wb*mid; block 0 warps 4-7 also compute W2*mid
    for (int d = tid; d < D_SZ; d += NT) s_v[d] = g_mid[d];
    __syncthreads();
    if (w < 3 && drow < D_SZ) {
        float p = warp_dot_pre(wB0, wB1, wB2, s_v4, lane);
        if (lane == 0) g_t[drow] = p;
    } else if (b == 0 && w >= 4 && w < 4 + C_SZ) {
        float p = warp_dot_pre(wC0, wC1, wC2, s_v4, lane);
        if (lane == 0) g_w2mid[w - 4] = p;
    }
    gbar(3);

    // ---- Phase E: scores/exp/psum + unnormalized weighted sum + y, all smem
    for (int d = tid; d < D_SZ; d += NT) s_v[d] = g_t[d];
    __syncthreads();
    {
        const float bias = __ldg(bb);
        #pragma unroll
        for (int j = 0; j < 2; j++) {
            const int r = w * 2 + j;
            float p = dot4(s_emb[r][lane], s_v4[lane])
                    + dot4(s_emb[r][lane + 32], s_v4[lane + 32]);
            if (lane < D4 - 64) p += dot4(s_emb[r][lane + 64], s_v4[lane + 64]);
            p = warp_sum(p);
            if (lane == 0) s_sc[r] = p + bias;
        }
    }
    __syncthreads();
    if (w == 0) {                   // scores tiny -> unshifted exp exact-safe
        float e = expf(s_sc[lane]);
        s_e[lane] = e;
        float ps = warp_sum(e);
        if (lane == 0) g_psum[b] = ps;
    }
    __syncthreads();
    if (tid < D_SZ) {               // weighted sum with raw e (pure smem)
        const int c = tid % D4, g = tid / D4;
        float4 acc = z;
        #pragma unroll
        for (int k = 0; k < 8; k++) {
            const int r = g * 8 + k;
            const float wt = s_e[r];
            float4 v = s_emb[r][c];
            acc.x = fmaf(wt, v.x, acc.x); acc.y = fmaf(wt, v.y, acc.y);
            acc.z = fmaf(wt, v.z, acc.z); acc.w = fmaf(wt, v.w, acc.w);
        }
        s_acc[g][c] = acc;
    }
    __syncthreads();
    if (tid < D4) {                 // t consumed: reuse s_v4 for the partial
        float4 t0 = s_acc[0][tid], t1 = s_acc[1][tid];
        float4 t2 = s_acc[2][tid], t3 = s_acc[3][tid];
        s_v4[tid] = make_float4((t0.x + t1.x) + (t2.x + t3.x),
                                (t0.y + t1.y) + (t2.y + t3.y),
                                (t0.z + t1.z) + (t2.z + t3.z),
                                (t0.w + t1.w) + (t2.w + t3.w));
    }
    __syncthreads();
    if (w >= 4 && w < 4 + C_SZ) {   // y_b[c] = W2[c,:] . block_partial
        float p = warp_dot_pre(wC0, wC1, wC2, s_v4, lane);
        if (lane == 0) g_y[(w - 4) * NB + b] = p;
    }
    gbar(4);

    // ---- Phase F: redundant total (identical order), rewards, logits
    if (w == 0) {
        float v = (g_psum[lane] + g_psum[lane + 32])
                + (g_psum[lane + 64] + g_psum[lane + 96]);
        v = warp_sum(v);
        if (lane == 0) s_bc = 1.0f / v;
    }
    __syncthreads();
    const float inv = s_bc;
    if (tid < RPB)
        out[C_SZ + b * RPB + tid] = s_e[tid] * inv;

    if (b == 0 && w < C_SZ) {
        const float* yy = g_y + (long)w * NB;
        float v = (yy[lane] + yy[lane + 32]) + (yy[lane + 64] + yy[lane + 96]);
        v = warp_sum(v);
        if (lane == 0)
            out[w] = g_w2mid[w] + v * inv * (1.0f / S_SZ) + __ldg(&b2[w]);
    }
}

// ---------------------------------------------------------------------------
extern "C" void kernel_launch(void* const* d_in, const int* in_sizes, int n_in,
                              void* d_out, int out_size)
{
    const int*   x   = (const int*)  d_in[0];
    const float* emb = (const float*)d_in[1];
    const float* W1  = (const float*)d_in[2];
    const float* b1  = (const float*)d_in[3];
    const float* Wb  = (const float*)d_in[4];
    const float* bb  = (const float*)d_in[5];
    const float* W2  = (const float*)d_in[6];
    const float* b2  = (const float*)d_in[7];
    float* out = (float*)d_out;   // out[0:4] = output, out[4:4100] = reward

    fused<<<NB, NT>>>(x, emb, W1, b1, Wb, bb, W2, b2, out);
}